// round 14
// baseline (speedup 1.0000x reference)
#include <cuda_runtime.h>
#include <math.h>

#define B_  8
#define T_  4096
#define D_  1024
#define A_  32
#define S_  16
#define H_  256
#define W_  (H_ - S_ + 1)   // 241
#define NT  256
#define NPAIR (B_ * A_)     // 256
#define NPR  (NPAIR / 2)    // 128 anchor-pair tasks

// scratch: every slot written every launch
__device__ float g_w [NPR][2][2][D_];   // [pairTask][half][window][d]
__device__ float g_sc[NPR][2][2];       // [pairTask][half][window] shift partial

__device__ __forceinline__ unsigned long long compat_mask_of(int r) {
    switch (r) {
        case 11: return (1ull<<11)|(1ull<<13)|(1ull<<16);
        case 21: return (1ull<<14)|(1ull<<15)|(1ull<<21)|(1ull<<22)|(1ull<<23);
        case 31: return (1ull<<15)|(1ull<<31)|(1ull<<32)|(1ull<<33);
        case 41: return (1ull<<41)|(1ull<<42)|(1ull<<43)|(1ull<<44);
        case 51: return (1ull<<15)|(1ull<<51)|(1ull<<52)|(1ull<<53);
        default: return 0ull;
    }
}

__constant__ signed char c_alias[64] = {
    -1,-1,-1,-1,-1,-1,-1,-1,-1,-1,
    -1,11,-1,11,-1,-1,11,-1,-1,-1,
    -1,21,21,21,-1,-1,-1,-1,-1,-1,
    -1,31,31,31,-1,-1,-1,-1,-1,-1,
    -1,41,41,41,41,-1,-1,-1,-1,-1,
    -1,51,51,51,-1,-1,-1,-1,-1,-1,
    -1,-1,-1,-1
};

__device__ __forceinline__ float warpSum(float v) {
    #pragma unroll
    for (int o = 16; o > 0; o >>= 1) v += __shfl_xor_sync(0xffffffffu, v, o);
    return v;
}

__device__ __forceinline__ int warpRank32(int ae, int lane) {
    int rank = 0;
    #pragma unroll
    for (int j = 0; j < 32; j++) {
        int aj = __shfl_sync(0xffffffffu, ae, j);
        rank += (aj < ae) || (aj == ae && j < lane);
    }
    return rank;
}

// ---------------------------------------------------------------------------
// KA: union stream, two phases per CTA. Hot loop has NO shuffles, NO sqrt:
// per-lane ||f-a||^2 partial goes to a padded smem row buffer (STS only);
// per-phase barriered post-pass does the row sums + sqrt + block reduce.
// ---------------------------------------------------------------------------
__global__ __launch_bounds__(NT, 2)
void ka_stream(const float* __restrict__ hidden,
               const float* __restrict__ anchor_repr,
               const int*   __restrict__ anchor_end)
{
    __shared__ float s_ws[8][D_];      // 32 KB per-warp colsum staging (reused per phase)
    __shared__ float s_ssv[256][33];   // ~34 KB per-row per-lane ||f-a||^2 partials
    __shared__ float s_red[8];
    __shared__ int   s_info[4];        // s0, s1, id0, id1

    const int P    = blockIdx.x >> 1;
    const int half = blockIdx.x & 1;
    const int b    = P >> 4;
    const int p    = P & 15;
    const int tid  = threadIdx.x;
    const int lane = tid & 31;
    const int warp = tid >> 5;

    if (warp == 0) {
        int ae = anchor_end[b * A_ + lane];
        int rank = warpRank32(ae, lane);
        if (rank == 2 * p)     { s_info[0] = ae + 1; s_info[2] = lane; }
        if (rank == 2 * p + 1) { s_info[1] = ae + 1; s_info[3] = lane; }
    }
    __syncthreads();

    const int s0  = s_info[0];
    const int s1  = s_info[1];
    const int gap = s1 - s0;           // >= 0
    const int L   = gap + H_;
    const int i0  = half ? (L >> 1) : 0;
    const int i1  = half ? L : (L >> 1);

    #pragma unroll 1
    for (int phase = 0; phase < 2; phase++) {
        const int aid = phase ? s_info[3] : s_info[2];
        const int lo  = phase ? max(i0, gap) : i0;
        const int hi  = phase ? i1 : min(i1, H_);
        const int n   = hi - lo;       // <= 256 by construction

        // stage this phase's anchor into registers
        const float4* ap = reinterpret_cast<const float4*>(
            anchor_repr + ((size_t)(b * A_ + aid)) * D_);
        float4 a[8];
        #pragma unroll
        for (int q = 0; q < 8; q++) a[q] = ap[q * 32 + lane];

        float4 w[8];
        #pragma unroll
        for (int q = 0; q < 8; q++) w[q] = make_float4(0.f,0.f,0.f,0.f);

        for (int r = lo + warp; r < hi; r += 8) {
            const float4* row = reinterpret_cast<const float4*>(
                hidden + ((size_t)(b * T_ + s0 + r)) * D_);
            float4 f[8];
            #pragma unroll
            for (int q = 0; q < 8; q++) f[q] = row[q * 32 + lane];

            float ssv = 0.f;
            #pragma unroll
            for (int q = 0; q < 8; q++) {
                float dx = f[q].x - a[q].x, dy = f[q].y - a[q].y;
                float dz = f[q].z - a[q].z, dw = f[q].w - a[q].w;
                ssv += dx*dx + dy*dy + dz*dz + dw*dw;
                w[q].x += f[q].x; w[q].y += f[q].y;
                w[q].z += f[q].z; w[q].w += f[q].w;
            }
            s_ssv[r - lo][lane] = ssv;   // STS, not in any dependency chain
        }

        // dump colsums (per-warp private slice, no sync needed yet)
        float4* wb = reinterpret_cast<float4*>(s_ws[warp]);
        #pragma unroll
        for (int q = 0; q < 8; q++) wb[q * 32 + lane] = w[q];
        __syncthreads();

        // colsum merge: thread tid owns float4 column tid
        {
            float4 acc = make_float4(0.f,0.f,0.f,0.f);
            #pragma unroll
            for (int ww = 0; ww < 8; ww++) {
                float4 v = reinterpret_cast<const float4*>(s_ws[ww])[tid];
                acc.x += v.x; acc.y += v.y; acc.z += v.z; acc.w += v.w;
            }
            reinterpret_cast<float4*>(&g_w[P][half][phase][0])[tid] = acc;
        }

        // shift post-pass: thread t = row slot t
        float sh = 0.f;
        if (tid < n) {
            float s = 0.f;
            #pragma unroll
            for (int i = 0; i < 32; i++) s += s_ssv[tid][i];
            sh = sqrtf(fmaxf(s, 0.f));
        }
        sh = warpSum(sh);
        if (lane == 0) s_red[warp] = sh;
        __syncthreads();                 // s_ssv reads complete here
        if (tid == 0) {
            float t = 0.f;
            #pragma unroll
            for (int ww = 0; ww < 8; ww++) t += s_red[ww];
            g_sc[P][half][phase] = t;
        }
        __syncthreads();                 // protect s_ws/s_ssv/s_red reuse
    }
}

// ---------------------------------------------------------------------------
// KB: per-anchor finalize. grid = NPAIR. (R11 version — measured 8.5 us.)
// ---------------------------------------------------------------------------
__global__ __launch_bounds__(NT, 4)
void kb_final(const float* __restrict__ anchor_repr,
              const int*   __restrict__ input_ids,
              const int*   __restrict__ anchor_end,
              float*       __restrict__ out)
{
    __shared__ float s_part[8][6];
    __shared__ float s_res[6];
    __shared__ int   s_ftok[H_];
    __shared__ int   s_span[S_];
    __shared__ int   s_alias[64];
    __shared__ int   s_root, s_has, s_ffmask;
    __shared__ float s_invdenom;
    __shared__ int   s_info[2];

    const int rank = blockIdx.x & 31;
    const int b    = blockIdx.x >> 5;
    const int tid  = threadIdx.x;
    const int lane = tid & 31;
    const int warp = tid >> 5;

    if (warp == 0) {
        int ae = anchor_end[b * A_ + lane];
        int r = warpRank32(ae, lane);
        if (r == rank) { s_info[0] = ae; s_info[1] = lane; }
    }
    if (tid < 64) s_alias[tid] = (int)c_alias[tid];
    __syncthreads();

    const int aend = s_info[0];
    const int orig = s_info[1];
    const int start = aend + 1;
    const int P = b * 16 + (rank >> 1);
    const int w = rank & 1;
    const int pair_out = b * A_ + orig;

    s_ftok[tid] = input_ids[b * T_ + start + tid];   // H_ == NT
    if (tid < S_) s_span[tid] = input_ids[b * T_ + aend - S_ + 1 + tid];
    __syncthreads();

    float4 u0 = reinterpret_cast<const float4*>(&g_w[P][0][w][0])[tid];
    float4 u1 = reinterpret_cast<const float4*>(&g_w[P][1][w][0])[tid];
    float4 Sv = make_float4(u0.x+u1.x, u0.y+u1.y, u0.z+u1.z, u0.w+u1.w);
    const float4 a4 = reinterpret_cast<const float4*>(
        anchor_repr + ((size_t)pair_out) * D_)[tid];

    float dotp = Sv.x*a4.x + Sv.y*a4.y + Sv.z*a4.z + Sv.w*a4.w;
    float nf2p = Sv.x*Sv.x + Sv.y*Sv.y + Sv.z*Sv.z + Sv.w*Sv.w;
    float na2p = a4.x*a4.x + a4.y*a4.y + a4.z*a4.z + a4.w*a4.w;

    const int anchor_tok = s_span[S_ - 1];
    float teq = (s_ftok[tid] == anchor_tok) ? 1.0f : 0.0f;

    #pragma unroll
    for (int o = 16; o > 0; o >>= 1) {
        dotp += __shfl_xor_sync(0xffffffffu, dotp, o);
        nf2p += __shfl_xor_sync(0xffffffffu, nf2p, o);
        na2p += __shfl_xor_sync(0xffffffffu, na2p, o);
        teq  += __shfl_xor_sync(0xffffffffu, teq,  o);
    }
    if (lane == 0) {
        s_part[warp][0] = dotp; s_part[warp][1] = nf2p;
        s_part[warp][2] = na2p; s_part[warp][3] = teq;
    }
    __syncthreads();

    if (warp == 0) {
        int tok = (lane < S_) ? s_span[lane] : (64 + lane);
        int cnt = 0; bool first = true;
        #pragma unroll
        for (int j = 0; j < S_; j++) {
            int tj = __shfl_sync(0xffffffffu, tok, j);
            cnt += (tj == tok);
            if (j < lane && tj == tok) first = false;
        }
        unsigned fb = __ballot_sync(0xffffffffu, (lane < S_) && first);
        int al = (lane < S_ && tok < 64) ? s_alias[tok] : -1;
        unsigned ab = __ballot_sync(0xffffffffu, al >= 0);
        int root;
        if (ab) {
            root = __shfl_sync(0xffffffffu, al, __ffs(ab) - 1);
        } else {
            int m = (lane < S_) ? cnt : 0;
            #pragma unroll
            for (int o = 16; o > 0; o >>= 1) m = max(m, __shfl_xor_sync(0xffffffffu, m, o));
            int cand = (lane < S_ && cnt == m) ? tok : 64;
            #pragma unroll
            for (int o = 16; o > 0; o >>= 1) cand = min(cand, __shfl_xor_sync(0xffffffffu, cand, o));
            root = cand;
        }
        if (lane == 0) {
            s_root = root;
            s_has = (compat_mask_of(root) != 0ull) ? 1 : 0;
            s_ffmask = (int)fb;
            s_invdenom = 1.0f / (float)__popc(fb);
        }
    }
    if (warp == 1 && lane == 0) {
        float d = 0.f, n = 0.f, na = 0.f, t = 0.f;
        #pragma unroll
        for (int ww = 0; ww < 8; ww++) {
            d += s_part[ww][0]; n += s_part[ww][1];
            na += s_part[ww][2]; t += s_part[ww][3];
        }
        s_res[0] = d; s_res[1] = n; s_res[2] = na; s_res[3] = t;
    }
    __syncthreads();

    const float invH = 1.0f / (float)H_;
    const float eps = 1e-8f;
    const float dot = s_res[0], nf2 = s_res[1], na2 = s_res[2];
    const float nr = fmaxf(sqrtf(na2), eps);
    const float nf = fmaxf(sqrtf(nf2) * invH, eps);
    const float sim = (dot * invH) / (nr * nf);
    const float hidden_c = fmaxf(0.0f, (1.0f - sim) * 0.5f);
    const float token_c = 1.0f - s_res[3] * invH;
    const float future_shift = (g_sc[P][0][w] + g_sc[P][1][w]) * invH;

    const int root = s_root;
    const int has = s_has;
    const int ffmask = s_ffmask;
    const float invdenom = s_invdenom;
    const unsigned long long cmask = compat_mask_of(root);

    float sims = 0.0f, rp_mean = 0.0f, regime = 0.0f, hit06 = 0.0f, best_v = -1e30f;
    if (tid < W_) {
        float ex = 0.0f, pos = 0.0f, rp = 0.0f, ac = 0.0f, hd = 0.0f;
        unsigned long long wmask = 0ull;
        #pragma unroll
        for (int s = 0; s < S_; s++) {
            int tok = s_ftok[tid + s];
            wmask |= (1ull << tok);
            float eq = (tok == s_span[s]) ? 1.0f : 0.0f;
            ex  += eq;
            pos += eq * ((1.0f - 0.04f * (float)s) * (1.0f / 11.2f));
            rp  += (tok == root) ? 1.0f : 0.0f;
            ac  += (s_alias[tok] == root) ? 1.0f : 0.0f;
            hd  += (float)((cmask >> tok) & 1ull);
        }
        float ov = 0.0f;
        #pragma unroll
        for (int s = 0; s < S_; s++) {
            if (((ffmask >> s) & 1) && ((wmask >> s_span[s]) & 1ull)) ov += 1.0f;
        }
        ov *= invdenom;
        const float inv16 = 1.0f / 16.0f;
        ex *= inv16; ac *= inv16; hd *= inv16;
        rp_mean = rp * inv16;

        regime = has ? (0.55f*hd + 0.2f*ov + 0.15f*ac + 0.1f*rp_mean)
                     : (0.45f*ex + 0.3f*ov + 0.1f*ac + 0.15f*rp_mean);
        sims = 0.25f*ex + 0.15f*ov + 0.35f*pos + 0.25f*regime;
        best_v = sims;
        hit06 = (sims >= 0.6f) ? 1.0f : 0.0f;
    }

    float v0 = sims, v1 = rp_mean, v2 = regime, v3 = hit06, v4 = best_v;
    #pragma unroll
    for (int o = 16; o > 0; o >>= 1) {
        v0 += __shfl_xor_sync(0xffffffffu, v0, o);
        v1 += __shfl_xor_sync(0xffffffffu, v1, o);
        v2 += __shfl_xor_sync(0xffffffffu, v2, o);
        v3 += __shfl_xor_sync(0xffffffffu, v3, o);
        v4 = fmaxf(v4, __shfl_xor_sync(0xffffffffu, v4, o));
    }
    if (lane == 0) {
        s_part[warp][0] = v0; s_part[warp][1] = v1; s_part[warp][2] = v2;
        s_part[warp][3] = v3; s_part[warp][4] = v4;
    }
    __syncthreads();

    if (tid == 0) {
        float sum_sims = 0.f, sum_rp = 0.f, sum_reg = 0.f, cnt06 = 0.f, best = -1e30f;
        #pragma unroll
        for (int ww = 0; ww < 8; ww++) {
            sum_sims += s_part[ww][0]; sum_rp += s_part[ww][1];
            sum_reg  += s_part[ww][2]; cnt06  += s_part[ww][3];
            best = fmaxf(best, s_part[ww][4]);
        }
        const float invW = 1.0f / (float)W_;
        float mrp = sum_rp  * invW;
        float mrc = sum_reg * invW;
        float mean_sims = sum_sims * invW;
        float dmass = cnt06 * invW;
        float dcoh = 0.6f*mean_sims + 0.25f*mrp + 0.15f*mrc;
        float pattern_c = 1.0f - (0.6f*best + 0.2f*mrp + 0.2f*mrc);
        float contr = 0.2f*hidden_c + 0.2f*token_c + 0.6f*pattern_c;
        contr = fminf(fmaxf(contr, 0.0f), 1.0f);

        out[0 * NPAIR + pair_out] = contr;
        out[1 * NPAIR + pair_out] = future_shift;
        out[2 * NPAIR + pair_out] = sim;
        out[3 * NPAIR + pair_out] = hidden_c;
        out[4 * NPAIR + pair_out] = token_c;
        out[5 * NPAIR + pair_out] = pattern_c;
        out[6 * NPAIR + pair_out] = dmass;
        out[7 * NPAIR + pair_out] = dcoh;
    }
}

extern "C" void kernel_launch(void* const* d_in, const int* in_sizes, int n_in,
                              void* d_out, int out_size) {
    const float* hidden      = (const float*)d_in[0];
    const float* anchor_repr = (const float*)d_in[1];
    const int*   input_ids   = (const int*)d_in[2];
    const int*   anchor_end  = (const int*)d_in[3];
    float*       out         = (float*)d_out;
    ka_stream<<<2 * NPR, NT>>>(hidden, anchor_repr, anchor_end);
    kb_final<<<NPAIR, NT>>>(anchor_repr, input_ids, anchor_end, out);
}

// round 15
// speedup vs baseline: 1.1645x; 1.1645x over previous
#include <cuda_runtime.h>
#include <math.h>

#define B_  8
#define T_  4096
#define D_  1024
#define A_  32
#define S_  16
#define H_  256
#define W_  (H_ - S_ + 1)   // 241
#define NT  256
#define NPAIR (B_ * A_)     // 256
#define NPR  (NPAIR / 2)    // 128 anchor-pair tasks

typedef unsigned long long u64;

// packed f32x2 ops (sm_10x): d = a*b + d ; d = a + d
#define FMA2(acc, x, y) asm volatile("fma.rn.f32x2 %0, %1, %2, %0;" : "+l"(acc) : "l"(x), "l"(y))
#define ADD2(acc, x)    asm volatile("add.rn.f32x2 %0, %1, %0;"     : "+l"(acc) : "l"(x))
#define UNPACK2(lo, hi, v) asm volatile("mov.b64 {%0, %1}, %2;" : "=f"(lo), "=f"(hi) : "l"(v))

// scratch: every slot written every launch
__device__ float g_w [NPR][2][2][D_];   // [pairTask][half][window][d]
__device__ float g_sc[NPR][2][2];       // [pairTask][half][window] shift partial

__device__ __forceinline__ unsigned long long compat_mask_of(int r) {
    switch (r) {
        case 11: return (1ull<<11)|(1ull<<13)|(1ull<<16);
        case 21: return (1ull<<14)|(1ull<<15)|(1ull<<21)|(1ull<<22)|(1ull<<23);
        case 31: return (1ull<<15)|(1ull<<31)|(1ull<<32)|(1ull<<33);
        case 41: return (1ull<<41)|(1ull<<42)|(1ull<<43)|(1ull<<44);
        case 51: return (1ull<<15)|(1ull<<51)|(1ull<<52)|(1ull<<53);
        default: return 0ull;
    }
}

__constant__ signed char c_alias[64] = {
    -1,-1,-1,-1,-1,-1,-1,-1,-1,-1,
    -1,11,-1,11,-1,-1,11,-1,-1,-1,
    -1,21,21,21,-1,-1,-1,-1,-1,-1,
    -1,31,31,31,-1,-1,-1,-1,-1,-1,
    -1,41,41,41,41,-1,-1,-1,-1,-1,
    -1,51,51,51,-1,-1,-1,-1,-1,-1,
    -1,-1,-1,-1
};

__device__ __forceinline__ float warpSum(float v) {
    #pragma unroll
    for (int o = 16; o > 0; o >>= 1) v += __shfl_xor_sync(0xffffffffu, v, o);
    return v;
}

__device__ __forceinline__ int warpRank32(int ae, int lane) {
    int rank = 0;
    #pragma unroll
    for (int j = 0; j < 32; j++) {
        int aj = __shfl_sync(0xffffffffu, ae, j);
        rank += (aj < ae) || (aj == ae && j < lane);
    }
    return rank;
}

// ---------------------------------------------------------------------------
// KA: R11 structure (two phases per CTA, anchor in regs, no LDS in chain),
// but all per-element math in PACKED f32x2 => 6 FMA-pipe ops per float4
// instead of 12. Issue-bound fix.
// ---------------------------------------------------------------------------
__global__ __launch_bounds__(NT, 2)
void ka_stream(const float* __restrict__ hidden,
               const float* __restrict__ anchor_repr,
               const int*   __restrict__ anchor_end)
{
    __shared__ float s_ws[2][8][D_];   // 64 KB: [window][warp][d]
    __shared__ float s_shw[2][8];
    __shared__ int   s_info[4];        // s0, s1, id0, id1

    const int P    = blockIdx.x >> 1;
    const int half = blockIdx.x & 1;
    const int b    = P >> 4;
    const int p    = P & 15;
    const int tid  = threadIdx.x;
    const int lane = tid & 31;
    const int warp = tid >> 5;

    if (warp == 0) {
        int ae = anchor_end[b * A_ + lane];
        int rank = warpRank32(ae, lane);
        if (rank == 2 * p)     { s_info[0] = ae + 1; s_info[2] = lane; }
        if (rank == 2 * p + 1) { s_info[1] = ae + 1; s_info[3] = lane; }
    }
    __syncthreads();

    const int s0  = s_info[0];
    const int s1  = s_info[1];
    const int gap = s1 - s0;           // >= 0
    const int L   = gap + H_;
    const int i0  = half ? (L >> 1) : 0;
    const int i1  = half ? L : (L >> 1);

    #pragma unroll 1
    for (int phase = 0; phase < 2; phase++) {
        const int aid = phase ? s_info[3] : s_info[2];
        const int lo  = phase ? max(i0, gap) : i0;
        const int hi  = phase ? i1 : min(i1, H_);

        // stage this phase's anchor into registers as packed f32x2 pairs
        const ulonglong2* ap = reinterpret_cast<const ulonglong2*>(
            anchor_repr + ((size_t)(b * A_ + aid)) * D_);
        u64 a2[16];
        #pragma unroll
        for (int q = 0; q < 8; q++) {
            ulonglong2 v = ap[q * 32 + lane];
            a2[2*q] = v.x; a2[2*q+1] = v.y;
        }

        // |a|^2 (packed accumulate, unpack once)
        u64 pa2 = 0ull;
        #pragma unroll
        for (int q = 0; q < 16; q++) FMA2(pa2, a2[q], a2[q]);
        float pal, pah; UNPACK2(pal, pah, pa2);
        const float na2 = warpSum(pal + pah);

        u64 w2[16];
        #pragma unroll
        for (int q = 0; q < 16; q++) w2[q] = 0ull;
        float sh = 0.f;

        for (int r = lo + warp; r < hi; r += 8) {
            const ulonglong2* row = reinterpret_cast<const ulonglong2*>(
                hidden + ((size_t)(b * T_ + s0 + r)) * D_);
            u64 nrm2 = 0ull, dot2 = 0ull;
            #pragma unroll
            for (int q = 0; q < 8; q++) {
                ulonglong2 f = row[q * 32 + lane];
                ADD2(w2[2*q],   f.x);
                ADD2(w2[2*q+1], f.y);
                FMA2(nrm2, f.x, f.x);
                FMA2(nrm2, f.y, f.y);
                FMA2(dot2, f.x, a2[2*q]);
                FMA2(dot2, f.y, a2[2*q+1]);
            }
            float nl, nh, dl, dh;
            UNPACK2(nl, nh, nrm2);
            UNPACK2(dl, dh, dot2);
            float nrm = nl + nh, dot = dl + dh;
            #pragma unroll
            for (int o = 16; o > 0; o >>= 1) {
                nrm += __shfl_xor_sync(0xffffffffu, nrm, o);
                dot += __shfl_xor_sync(0xffffffffu, dot, o);
            }
            if (lane == 0) sh += sqrtf(fmaxf(nrm - 2.f*dot + na2, 0.f));
        }

        // dump register colsums to this warp's private slice (STS.128, once)
        ulonglong2* wb = reinterpret_cast<ulonglong2*>(s_ws[phase][warp]);
        #pragma unroll
        for (int q = 0; q < 8; q++) wb[q * 32 + lane] = make_ulonglong2(w2[2*q], w2[2*q+1]);
        if (lane == 0) s_shw[phase][warp] = sh;
    }
    __syncthreads();

    // tree-merge 8 warp slices per window; thread tid owns float4 column tid
    #pragma unroll
    for (int win = 0; win < 2; win++) {
        float4 acc = make_float4(0.f,0.f,0.f,0.f);
        #pragma unroll
        for (int w = 0; w < 8; w++) {
            float4 v = reinterpret_cast<const float4*>(s_ws[win][w])[tid];
            acc.x += v.x; acc.y += v.y; acc.z += v.z; acc.w += v.w;
        }
        reinterpret_cast<float4*>(&g_w[P][half][win][0])[tid] = acc;
    }
    if (tid == 0) {
        float t0 = 0.f, t1 = 0.f;
        #pragma unroll
        for (int w = 0; w < 8; w++) { t0 += s_shw[0][w]; t1 += s_shw[1][w]; }
        g_sc[P][half][0] = t0;
        g_sc[P][half][1] = t1;
    }
}

// ---------------------------------------------------------------------------
// KB: per-anchor finalize. grid = NPAIR. (R11 version — measured 8.5 us.)
// ---------------------------------------------------------------------------
__global__ __launch_bounds__(NT, 4)
void kb_final(const float* __restrict__ anchor_repr,
              const int*   __restrict__ input_ids,
              const int*   __restrict__ anchor_end,
              float*       __restrict__ out)
{
    __shared__ float s_part[8][6];
    __shared__ float s_res[6];
    __shared__ int   s_ftok[H_];
    __shared__ int   s_span[S_];
    __shared__ int   s_alias[64];
    __shared__ int   s_root, s_has, s_ffmask;
    __shared__ float s_invdenom;
    __shared__ int   s_info[2];

    const int rank = blockIdx.x & 31;
    const int b    = blockIdx.x >> 5;
    const int tid  = threadIdx.x;
    const int lane = tid & 31;
    const int warp = tid >> 5;

    if (warp == 0) {
        int ae = anchor_end[b * A_ + lane];
        int r = warpRank32(ae, lane);
        if (r == rank) { s_info[0] = ae; s_info[1] = lane; }
    }
    if (tid < 64) s_alias[tid] = (int)c_alias[tid];
    __syncthreads();

    const int aend = s_info[0];
    const int orig = s_info[1];
    const int start = aend + 1;
    const int P = b * 16 + (rank >> 1);
    const int w = rank & 1;
    const int pair_out = b * A_ + orig;

    s_ftok[tid] = input_ids[b * T_ + start + tid];   // H_ == NT
    if (tid < S_) s_span[tid] = input_ids[b * T_ + aend - S_ + 1 + tid];
    __syncthreads();

    float4 u0 = reinterpret_cast<const float4*>(&g_w[P][0][w][0])[tid];
    float4 u1 = reinterpret_cast<const float4*>(&g_w[P][1][w][0])[tid];
    float4 Sv = make_float4(u0.x+u1.x, u0.y+u1.y, u0.z+u1.z, u0.w+u1.w);
    const float4 a4 = reinterpret_cast<const float4*>(
        anchor_repr + ((size_t)pair_out) * D_)[tid];

    float dotp = Sv.x*a4.x + Sv.y*a4.y + Sv.z*a4.z + Sv.w*a4.w;
    float nf2p = Sv.x*Sv.x + Sv.y*Sv.y + Sv.z*Sv.z + Sv.w*Sv.w;
    float na2p = a4.x*a4.x + a4.y*a4.y + a4.z*a4.z + a4.w*a4.w;

    const int anchor_tok = s_span[S_ - 1];
    float teq = (s_ftok[tid] == anchor_tok) ? 1.0f : 0.0f;

    #pragma unroll
    for (int o = 16; o > 0; o >>= 1) {
        dotp += __shfl_xor_sync(0xffffffffu, dotp, o);
        nf2p += __shfl_xor_sync(0xffffffffu, nf2p, o);
        na2p += __shfl_xor_sync(0xffffffffu, na2p, o);
        teq  += __shfl_xor_sync(0xffffffffu, teq,  o);
    }
    if (lane == 0) {
        s_part[warp][0] = dotp; s_part[warp][1] = nf2p;
        s_part[warp][2] = na2p; s_part[warp][3] = teq;
    }
    __syncthreads();

    if (warp == 0) {
        int tok = (lane < S_) ? s_span[lane] : (64 + lane);
        int cnt = 0; bool first = true;
        #pragma unroll
        for (int j = 0; j < S_; j++) {
            int tj = __shfl_sync(0xffffffffu, tok, j);
            cnt += (tj == tok);
            if (j < lane && tj == tok) first = false;
        }
        unsigned fb = __ballot_sync(0xffffffffu, (lane < S_) && first);
        int al = (lane < S_ && tok < 64) ? s_alias[tok] : -1;
        unsigned ab = __ballot_sync(0xffffffffu, al >= 0);
        int root;
        if (ab) {
            root = __shfl_sync(0xffffffffu, al, __ffs(ab) - 1);
        } else {
            int m = (lane < S_) ? cnt : 0;
            #pragma unroll
            for (int o = 16; o > 0; o >>= 1) m = max(m, __shfl_xor_sync(0xffffffffu, m, o));
            int cand = (lane < S_ && cnt == m) ? tok : 64;
            #pragma unroll
            for (int o = 16; o > 0; o >>= 1) cand = min(cand, __shfl_xor_sync(0xffffffffu, cand, o));
            root = cand;
        }
        if (lane == 0) {
            s_root = root;
            s_has = (compat_mask_of(root) != 0ull) ? 1 : 0;
            s_ffmask = (int)fb;
            s_invdenom = 1.0f / (float)__popc(fb);
        }
    }
    if (warp == 1 && lane == 0) {
        float d = 0.f, n = 0.f, na = 0.f, t = 0.f;
        #pragma unroll
        for (int ww = 0; ww < 8; ww++) {
            d += s_part[ww][0]; n += s_part[ww][1];
            na += s_part[ww][2]; t += s_part[ww][3];
        }
        s_res[0] = d; s_res[1] = n; s_res[2] = na; s_res[3] = t;
    }
    __syncthreads();

    const float invH = 1.0f / (float)H_;
    const float eps = 1e-8f;
    const float dot = s_res[0], nf2 = s_res[1], na2 = s_res[2];
    const float nr = fmaxf(sqrtf(na2), eps);
    const float nf = fmaxf(sqrtf(nf2) * invH, eps);
    const float sim = (dot * invH) / (nr * nf);
    const float hidden_c = fmaxf(0.0f, (1.0f - sim) * 0.5f);
    const float token_c = 1.0f - s_res[3] * invH;
    const float future_shift = (g_sc[P][0][w] + g_sc[P][1][w]) * invH;

    const int root = s_root;
    const int has = s_has;
    const int ffmask = s_ffmask;
    const float invdenom = s_invdenom;
    const unsigned long long cmask = compat_mask_of(root);

    float sims = 0.0f, rp_mean = 0.0f, regime = 0.0f, hit06 = 0.0f, best_v = -1e30f;
    if (tid < W_) {
        float ex = 0.0f, pos = 0.0f, rp = 0.0f, ac = 0.0f, hd = 0.0f;
        unsigned long long wmask = 0ull;
        #pragma unroll
        for (int s = 0; s < S_; s++) {
            int tok = s_ftok[tid + s];
            wmask |= (1ull << tok);
            float eq = (tok == s_span[s]) ? 1.0f : 0.0f;
            ex  += eq;
            pos += eq * ((1.0f - 0.04f * (float)s) * (1.0f / 11.2f));
            rp  += (tok == root) ? 1.0f : 0.0f;
            ac  += (s_alias[tok] == root) ? 1.0f : 0.0f;
            hd  += (float)((cmask >> tok) & 1ull);
        }
        float ov = 0.0f;
        #pragma unroll
        for (int s = 0; s < S_; s++) {
            if (((ffmask >> s) & 1) && ((wmask >> s_span[s]) & 1ull)) ov += 1.0f;
        }
        ov *= invdenom;
        const float inv16 = 1.0f / 16.0f;
        ex *= inv16; ac *= inv16; hd *= inv16;
        rp_mean = rp * inv16;

        regime = has ? (0.55f*hd + 0.2f*ov + 0.15f*ac + 0.1f*rp_mean)
                     : (0.45f*ex + 0.3f*ov + 0.1f*ac + 0.15f*rp_mean);
        sims = 0.25f*ex + 0.15f*ov + 0.35f*pos + 0.25f*regime;
        best_v = sims;
        hit06 = (sims >= 0.6f) ? 1.0f : 0.0f;
    }

    float v0 = sims, v1 = rp_mean, v2 = regime, v3 = hit06, v4 = best_v;
    #pragma unroll
    for (int o = 16; o > 0; o >>= 1) {
        v0 += __shfl_xor_sync(0xffffffffu, v0, o);
        v1 += __shfl_xor_sync(0xffffffffu, v1, o);
        v2 += __shfl_xor_sync(0xffffffffu, v2, o);
        v3 += __shfl_xor_sync(0xffffffffu, v3, o);
        v4 = fmaxf(v4, __shfl_xor_sync(0xffffffffu, v4, o));
    }
    if (lane == 0) {
        s_part[warp][0] = v0; s_part[warp][1] = v1; s_part[warp][2] = v2;
        s_part[warp][3] = v3; s_part[warp][4] = v4;
    }
    __syncthreads();

    if (tid == 0) {
        float sum_sims = 0.f, sum_rp = 0.f, sum_reg = 0.f, cnt06 = 0.f, best = -1e30f;
        #pragma unroll
        for (int ww = 0; ww < 8; ww++) {
            sum_sims += s_part[ww][0]; sum_rp += s_part[ww][1];
            sum_reg  += s_part[ww][2]; cnt06  += s_part[ww][3];
            best = fmaxf(best, s_part[ww][4]);
        }
        const float invW = 1.0f / (float)W_;
        float mrp = sum_rp  * invW;
        float mrc = sum_reg * invW;
        float mean_sims = sum_sims * invW;
        float dmass = cnt06 * invW;
        float dcoh = 0.6f*mean_sims + 0.25f*mrp + 0.15f*mrc;
        float pattern_c = 1.0f - (0.6f*best + 0.2f*mrp + 0.2f*mrc);
        float contr = 0.2f*hidden_c + 0.2f*token_c + 0.6f*pattern_c;
        contr = fminf(fmaxf(contr, 0.0f), 1.0f);

        out[0 * NPAIR + pair_out] = contr;
        out[1 * NPAIR + pair_out] = future_shift;
        out[2 * NPAIR + pair_out] = sim;
        out[3 * NPAIR + pair_out] = hidden_c;
        out[4 * NPAIR + pair_out] = token_c;
        out[5 * NPAIR + pair_out] = pattern_c;
        out[6 * NPAIR + pair_out] = dmass;
        out[7 * NPAIR + pair_out] = dcoh;
    }
}

extern "C" void kernel_launch(void* const* d_in, const int* in_sizes, int n_in,
                              void* d_out, int out_size) {
    const float* hidden      = (const float*)d_in[0];
    const float* anchor_repr = (const float*)d_in[1];
    const int*   input_ids   = (const int*)d_in[2];
    const int*   anchor_end  = (const int*)d_in[3];
    float*       out         = (float*)d_out;
    ka_stream<<<2 * NPR, NT>>>(hidden, anchor_repr, anchor_end);
    kb_final<<<NPAIR, NT>>>(anchor_repr, input_ids, anchor_end, out);
}